// round 6
// baseline (speedup 1.0000x reference)
#include <cuda_runtime.h>
#include <cstdint>

// ---------------------------------------------------------------------------
// Blake2Cipher soft-hash, fp32 — R3: two elements per thread, all elementwise
// math in packed f32x2 (FFMA2/FADD2/FMUL2). MUFU (ex2/rcp/tanh), floor and
// flip-sensitive clamps stay scalar. Negation via sign-bit XOR (ALU pipe).
// ---------------------------------------------------------------------------

typedef unsigned long long f2;   // packed pair of fp32 (lo, hi)

__device__ __forceinline__ f2 pk(float lo, float hi) {
    f2 r; asm("mov.b64 %0, {%1, %2};" : "=l"(r) : "f"(lo), "f"(hi)); return r;
}
__device__ __forceinline__ void upk(f2 a, float& x, float& y) {
    asm("mov.b64 {%0, %1}, %2;" : "=f"(x), "=f"(y) : "l"(a));
}
__device__ __forceinline__ f2 add2(f2 a, f2 b) {
    f2 r; asm("add.rn.f32x2 %0, %1, %2;" : "=l"(r) : "l"(a), "l"(b)); return r;
}
__device__ __forceinline__ f2 mul2(f2 a, f2 b) {
    f2 r; asm("mul.rn.f32x2 %0, %1, %2;" : "=l"(r) : "l"(a), "l"(b)); return r;
}
__device__ __forceinline__ f2 fma2(f2 a, f2 b, f2 c) {
    f2 r; asm("fma.rn.f32x2 %0, %1, %2, %3;" : "=l"(r) : "l"(a), "l"(b), "l"(c)); return r;
}
__device__ __forceinline__ f2 neg2(f2 a) { return a ^ 0x8000000080000000ULL; }

__device__ __forceinline__ float ex2a(float x){ float r; asm("ex2.approx.f32 %0, %1;" : "=f"(r) : "f"(x)); return r; }
__device__ __forceinline__ float rcpa(float x){ float r; asm("rcp.approx.f32 %0, %1;" : "=f"(r) : "f"(x)); return r; }
__device__ __forceinline__ float tanha(float x){ float r; asm("tanh.approx.f32 %0, %1;" : "=f"(r) : "f"(x)); return r; }

__device__ __forceinline__ f2 ex2p(f2 w)  { float a,b; upk(w,a,b); return pk(ex2a(a),  ex2a(b)); }
__device__ __forceinline__ f2 tanhp(f2 w) { float a,b; upk(w,a,b); return pk(tanha(a), tanha(b)); }
__device__ __forceinline__ f2 rcpp(f2 w)  { float a,b; upk(w,a,b); return pk(rcpa(a),  rcpa(b)); }

#define K10   14.42695041f    // 10*log2(e)
#define KH     7.213475205f   // 5*log2(e)
#define SIG5   0.0066928509f  // sigmoid(-5)
#define SIG5S  0.066480567f   // d/dx sigmoid(10x-5) at x=0
#define TH25   0.98661430f    // tanh(2.5)
#define TH25S  0.13296110f    // d/dx tanh(5x-2.5) at x=0

// 8 sigmoids (4 pairs) sharing one NR-refined reciprocal per element.
// w = -z*log2(e); g = 1/(1+2^w). All elementwise ops packed.
__device__ __forceinline__ void sigb4(f2 w0, f2 w1, f2 w2, f2 w3,
                                      f2& g0, f2& g1, f2& g2, f2& g3, f2 ONEp) {
    f2 d0 = add2(ex2p(w0), ONEp);
    f2 d1 = add2(ex2p(w1), ONEp);
    f2 d2 = add2(ex2p(w2), ONEp);
    f2 d3 = add2(ex2p(w3), ONEp);
    f2 p01 = mul2(d0, d1), p23 = mul2(d2, d3);
    f2 P   = mul2(p01, p23);
    f2 r0  = rcpp(P);
    f2 er  = fma2(neg2(P), r0, ONEp);
    f2 R   = fma2(r0, er, r0);          // Newton-refined reciprocal
    f2 R01 = mul2(R, p23), R23 = mul2(R, p01);
    g0 = mul2(R01, d1); g1 = mul2(R01, d0);
    g2 = mul2(R23, d3); g3 = mul2(R23, d2);
}

// soft_xor in tanh form (unclamped; used only at contraction-protected spots)
__device__ __forceinline__ f2 sxt2(f2 tx, f2 ty, f2 ONEp, f2 cHP, f2 cSN) {
    f2 p  = mul2(tx, ty);
    f2 a0 = fma2(neg2(p), cHP, cHP);      // 0.5 - 0.5*p
    f2 q1 = fma2(neg2(tx), tx, ONEp);     // 1 - tx^2
    f2 q2 = fma2(neg2(ty), ty, ONEp);     // 1 - ty^2
    f2 qq = mul2(q1, q2);
    return fma2(qq, cSN, a0);             // cSN = -1/16
}

// Exact rotr<63> matching reference fp32 mod arithmetic
__device__ __forceinline__ float rot63(float x) {
    float t2  = x + x;
    float xs2 = x * 0x1p65f;
    float qq  = floorf(t2);
    float sl  = fmaf(qq, -0x1p64f, xs2);
    float sum = t2 + sl;
    return sum * 0x1p-64f;
}

// S10 scalar tail (flip-sensitive: clamp + exact rot63)
__device__ __forceinline__ float s10tail(float b, float ys) {
    float xs  = fmaf(b, SIG5S, SIG5);     // b is rot24-out (<=6e-8): linear exact
    float t1  = xs * (1.0f - ys);
    float t2  = (1.0f - xs) * ys;
    float u   = t1 + t2;
    float f   = __saturatef(fmaf(-t1, t2, u));
    return rot63(f);
}

// Packed soft_xor with scalar clamp (used for round-state outputs)
__device__ __forceinline__ f2 xorcomb(f2 xs, f2 ys, f2 ONEp) {
    f2 oys = add2(ONEp, neg2(ys));
    f2 oxs = add2(ONEp, neg2(xs));
    f2 t1  = mul2(xs, oys);
    f2 t2  = mul2(oxs, ys);
    f2 u   = add2(t1, t2);
    f2 res = fma2(neg2(t1), t2, u);
    float a, b; upk(res, a, b);
    return pk(__saturatef(a), __saturatef(b));
}

#define IVF(x) ((float)(x##ull) * 0x1p-64f)

__global__ void __launch_bounds__(128, 3)
blake2_soft_kernel(const float* __restrict__ msg, float* __restrict__ out, int batch) {
    int t = blockIdx.x * 128 + threadIdx.x;
    int npairs = (batch + 1) >> 1;
    if (t >= npairs) return;
    int iA = 2 * t;
    int iB = (2 * t + 1 < batch) ? (2 * t + 1) : (batch - 1);

    const float IVf[8] = {
        IVF(7640891576956012808), IVF(13503953896175478587),
        IVF(4354685564936845355), IVF(11912009170470909681),
        IVF(5840696475078001361), IVF(11170449401992604703),
        IVF(2270897969802886507), IVF(6620516959819538809)
    };

    // Hoisted packed constants
    const f2 ONEp   = pk(1.0f, 1.0f);
    const f2 K10p   = pk(K10, K10);
    const f2 nK10p  = pk(-K10, -K10);
    const f2 KHp    = pk(KH, KH);
    const f2 FIVEp  = pk(5.0f, 5.0f);
    const f2 n25p   = pk(-2.5f, -2.5f);
    const f2 TH25Sp = pk(TH25S, TH25S);
    const f2 nTH25p = pk(-TH25, -TH25);
    const f2 cHP    = pk(0.5f, 0.5f);
    const f2 cSN    = pk(-0.0625f, -0.0625f);
    const f2 S32p   = pk(0x1p-32f, 0x1p-32f);
    const f2 S24p   = pk(0x1p-24f, 0x1p-24f);
    const f2 S16p   = pk(0x1p-16f, 0x1p-16f);
    const f2 SIG5Sp = pk(SIG5S, SIG5S);
    const f2 SIG5p  = pk(SIG5, SIG5);

    f2 IVp[8];
#pragma unroll
    for (int j = 0; j < 8; j++) IVp[j] = pk(IVf[j], IVf[j]);

    // Column-S3 tx constants: d = IV[4+q] every round (v[12..15] reset to IV).
    // tanh error here is protected by the following *2^-32 contraction.
    f2 TXC[4];
#pragma unroll
    for (int q = 0; q < 4; q++) {
        float txc = tanha(fmaf(IVf[4 + q], 5.0f, -2.5f));
        TXC[q] = pk(txc, txc);
    }

    // Load 16 message words of both elements, pack pairwise.
    f2 m[16];
    {
        const float4* ma = reinterpret_cast<const float4*>(msg) + (size_t)iA * 4;
        const float4* mb = reinterpret_cast<const float4*>(msg) + (size_t)iB * 4;
#pragma unroll
        for (int k = 0; k < 4; k++) {
            float4 qa = ma[k], qb = mb[k];
            m[4 * k + 0] = pk(qa.x, qb.x);
            m[4 * k + 1] = pk(qa.y, qb.y);
            m[4 * k + 2] = pk(qa.z, qb.z);
            m[4 * k + 3] = pk(qa.w, qb.w);
        }
    }

    f2 v[16];
#pragma unroll
    for (int j = 0; j < 8; j++) v[j] = IVp[j];

#define IA(q) (q)
#define IB(q) (DIAG ? 4 + (((q) + 1) & 3) : 4 + (q))
#define IC(q) (DIAG ? 8 + (((q) + 2) & 3) : 8 + (q))
#define ID(q) (DIAG ? 12 + (((q) + 3) & 3) : 12 + (q))
#define IX(q) (DIAG ? 8 + 2 * (q) : 2 * (q))
#define IY(q) (DIAG ? 9 + 2 * (q) : 2 * (q) + 1)

// soft_add over 4 packed lanes: s = v+u; g = sigmoid(10(s-1)); v = s-g
#define SA4(TIDX, UEXPR)                                                     \
    {                                                                        \
        f2 s_[4], w_[4], g_[4];                                              \
        _Pragma("unroll") for (int q = 0; q < 4; q++) s_[q] = add2(v[TIDX], (UEXPR)); \
        _Pragma("unroll") for (int q = 0; q < 4; q++) w_[q] = fma2(s_[q], nK10p, K10p); \
        sigb4(w_[0], w_[1], w_[2], w_[3], g_[0], g_[1], g_[2], g_[3], ONEp); \
        _Pragma("unroll") for (int q = 0; q < 4; q++) v[TIDX] = add2(s_[q], neg2(g_[q])); \
    }

#define G4BODY()                                                             \
    {                                                                        \
        /* S1: a = sa(a, b) */                                               \
        SA4(IA(q), v[IB(q)]);                                                \
        /* S2: a = sa(a, m[x]) */                                            \
        SA4(IA(q), m[IX(q)]);                                                \
        /* S3: d = sx(d, a) * 2^-32  (protected) */                          \
        _Pragma("unroll") for (int q = 0; q < 4; q++) {                      \
            f2 ty = tanhp(fma2(v[IA(q)], FIVEp, n25p));                      \
            f2 tx = DIAG ? fma2(v[ID(q)], TH25Sp, nTH25p) : TXC[q];          \
            v[ID(q)] = mul2(sxt2(tx, ty, ONEp, cHP, cSN), S32p);             \
        }                                                                    \
        /* S4: c = sa(c, d) */                                               \
        SA4(IC(q), v[ID(q)]);                                                \
        /* S5: b = sx(b, c) * 2^-24  (protected) */                          \
        _Pragma("unroll") for (int q = 0; q < 4; q++) {                      \
            f2 tx = tanhp(fma2(v[IB(q)], FIVEp, n25p));                      \
            f2 ty = tanhp(fma2(v[IC(q)], FIVEp, n25p));                      \
            v[IB(q)] = mul2(sxt2(tx, ty, ONEp, cHP, cSN), S24p);             \
        }                                                                    \
        /* S6: a = sa(a, b) */                                               \
        SA4(IA(q), v[IB(q)]);                                                \
        /* S7: a = sa(a, m[y]) */                                            \
        SA4(IA(q), m[IY(q)]);                                                \
        /* S8: d = sx(d, a) * 2^-16  (protected; d is rot32-out: linear tx) */\
        _Pragma("unroll") for (int q = 0; q < 4; q++) {                      \
            f2 tx = fma2(v[ID(q)], TH25Sp, nTH25p);                          \
            f2 ty = tanhp(fma2(v[IA(q)], FIVEp, n25p));                      \
            v[ID(q)] = mul2(sxt2(tx, ty, ONEp, cHP, cSN), S16p);             \
        }                                                                    \
        /* S9: c = sa(c, d) */                                               \
        SA4(IC(q), v[ID(q)]);                                                \
        /* S10: b = rot63(sx(b, c))  (flip-sensitive: scalar tail) */        \
        {                                                                    \
            f2 wy_[4], ys_[4];                                               \
            _Pragma("unroll") for (int q = 0; q < 4; q++)                    \
                wy_[q] = fma2(v[IC(q)], nK10p, KHp);                         \
            sigb4(wy_[0], wy_[1], wy_[2], wy_[3],                            \
                  ys_[0], ys_[1], ys_[2], ys_[3], ONEp);                     \
            _Pragma("unroll") for (int q = 0; q < 4; q++) {                  \
                float b0, b1, y0, y1;                                        \
                upk(v[IB(q)], b0, b1); upk(ys_[q], y0, y1);                  \
                v[IB(q)] = pk(s10tail(b0, y0), s10tail(b1, y1));             \
            }                                                                \
        }                                                                    \
    }

#pragma unroll 1
    for (int r = 0; r < 10; r++) {
#pragma unroll
        for (int j = 0; j < 8; j++) v[8 + j] = IVp[j];

        { constexpr bool DIAG = false; G4BODY(); }   // column: 4 independent G
        { constexpr bool DIAG = true;  G4BODY(); }   // diagonal: 4 independent G

        // state = soft_xor(v[j], v[8+j]); batched sigmoids, clamped outputs.
        {
            f2 wx[4], xs[4], wy[4], ys[4];
#pragma unroll
            for (int j = 0; j < 4; j++) {
                wx[j] = fma2(v[j],     nK10p, KHp);
                wy[j] = fma2(v[8 + j], nK10p, KHp);
            }
            sigb4(wx[0], wx[1], wx[2], wx[3], xs[0], xs[1], xs[2], xs[3], ONEp);
            sigb4(wy[0], wy[1], wy[2], wy[3], ys[0], ys[1], ys[2], ys[3], ONEp);
#pragma unroll
            for (int j = 0; j < 4; j++) v[j] = xorcomb(xs[j], ys[j], ONEp);
        }
        {
            // j=4..7: v[8+j] is a rot16 output (<=1.6e-5): linear sigmoid exact
            f2 wx[4], xs[4];
#pragma unroll
            for (int j = 0; j < 4; j++) wx[j] = fma2(v[4 + j], nK10p, KHp);
            sigb4(wx[0], wx[1], wx[2], wx[3], xs[0], xs[1], xs[2], xs[3], ONEp);
#pragma unroll
            for (int j = 0; j < 4; j++) {
                f2 ysl = fma2(v[12 + j], SIG5Sp, SIG5p);
                v[4 + j] = xorcomb(xs[j], ysl, ONEp);
            }
        }
    }

    // Unpack and store both rows.
    float sA[8], sB[8];
#pragma unroll
    for (int j = 0; j < 8; j++) upk(v[j], sA[j], sB[j]);
    float4* oa = reinterpret_cast<float4*>(out) + (size_t)iA * 2;
    oa[0] = make_float4(sA[0], sA[1], sA[2], sA[3]);
    oa[1] = make_float4(sA[4], sA[5], sA[6], sA[7]);
    if (2 * t + 1 < batch) {
        float4* ob = reinterpret_cast<float4*>(out) + (size_t)iB * 2;
        ob[0] = make_float4(sB[0], sB[1], sB[2], sB[3]);
        ob[1] = make_float4(sB[4], sB[5], sB[6], sB[7]);
    }
}

extern "C" void kernel_launch(void* const* d_in, const int* in_sizes, int n_in,
                              void* d_out, int out_size) {
    const float* msg = (const float*)d_in[0];
    float* out = (float*)d_out;
    int batch = in_sizes[0] / 16;
    int npairs = (batch + 1) / 2;
    int blocks = (npairs + 127) / 128;
    blake2_soft_kernel<<<blocks, 128>>>(msg, out, batch);
}

// round 8
// speedup vs baseline: 1.2334x; 1.2334x over previous
#include <cuda_runtime.h>
#include <cstdint>

// ---------------------------------------------------------------------------
// Blake2Cipher soft-hash, fp32 — R7: scalar (R2 base) + instruction surgery.
//  * rot63 -> exact 2f / 2f-1 branchless select (proven vs reference fp32).
//  * S3/S8 soft_xors: constant-tx quadratic A + B*ty + C*ty^2, scale folded.
//  * S10 tail: xs const-folded quadratic in ys.
//  * sigb4 without Newton step on soft_add batches (kept on S10/final).
// ---------------------------------------------------------------------------

__device__ __forceinline__ float ex2a(float x){ float r; asm("ex2.approx.f32 %0, %1;" : "=f"(r) : "f"(x)); return r; }
__device__ __forceinline__ float rcpa(float x){ float r; asm("rcp.approx.f32 %0, %1;" : "=f"(r) : "f"(x)); return r; }
__device__ __forceinline__ float tanha(float x){ float r; asm("tanh.approx.f32 %0, %1;" : "=f"(r) : "f"(x)); return r; }

#define K10   14.42695041f    // 10*log2(e)
#define KH     7.213475205f   // 5*log2(e)
#define SIG5   0.0066928509f  // sigmoid(-5)
#define SIG5S  0.066480567f   // d/dx sigmoid(10x-5) at x=0
#define TH25   0.98661430f    // tanh(2.5)

// Folded constants for constant-tx soft_xor quadratics: tx = -TH25.
// sxt*scale = A + B*ty + C*ty^2 with D=(1-TH25^2)/16.
#define DQC   ((1.0f - TH25*TH25) * 0.0625f)
#define A32   ((0.5f - DQC) * 0x1p-32f)
#define B32   ((0.5f * TH25) * 0x1p-32f)
#define C32   (DQC * 0x1p-32f)
#define A16   ((0.5f - DQC) * 0x1p-16f)
#define B16   ((0.5f * TH25) * 0x1p-16f)
#define C16   (DQC * 0x1p-16f)

// S10 tail: f = soft_xor(xs=SIG5 const, ys) = S10A + S10B*ys + S10G*ys^2
#define S10A  (SIG5)
#define S10B  ((1.0f - 2.0f*SIG5) - SIG5*(1.0f - SIG5))
#define S10G  (SIG5*(1.0f - SIG5))

// batch-4 sigmoid; w = -z*log2(e); g = 1/(1+2^w); optional Newton refine.
template <bool NR>
__device__ __forceinline__ void sigb4(const float w[4], float g[4]) {
    float d0 = 1.0f + ex2a(w[0]);
    float d1 = 1.0f + ex2a(w[1]);
    float d2 = 1.0f + ex2a(w[2]);
    float d3 = 1.0f + ex2a(w[3]);
    float p01 = d0 * d1, p23 = d2 * d3;
    float P = p01 * p23;
    float R = rcpa(P);
    if (NR) {
        float er = fmaf(-P, R, 1.0f);
        R = fmaf(R, er, R);
    }
    float R01 = R * p23, R23 = R * p01;
    g[0] = R01 * d1; g[1] = R01 * d0;
    g[2] = R23 * d3; g[3] = R23 * d2;
}

// Exact rot63: f in [0,1] -> 2f (f<0.5) or 2f-1 (f>=0.5). Matches reference
// fp32 arithmetic bit-for-bit except f==0.5 exactly (diff 2^-64).
__device__ __forceinline__ float rot63f(float f) {
    float t = f + f;
    float r = t - 1.0f;
    return (t >= 1.0f) ? r : t;
}

// Cheap clamped soft_xor combine from precomputed sigmoids.
__device__ __forceinline__ float xorcomb(float xs, float ys) {
    float p = xs * ys;
    float s = xs + ys;
    float u = fmaf(p, -2.0f, s);      // t1+t2
    float q = (1.0f + p) - s;         // (1-xs)(1-ys)
    return __saturatef(fmaf(-p, q, u));
}

#define IVF(x) ((float)(x##ull) * 0x1p-64f)

__global__ void __launch_bounds__(128, 6)
blake2_soft_kernel(const float* __restrict__ msg, float* __restrict__ out, int batch) {
    int i = blockIdx.x * 128 + threadIdx.x;
    if (i >= batch) return;

    const float IVf[8] = {
        IVF(7640891576956012808), IVF(13503953896175478587),
        IVF(4354685564936845355), IVF(11912009170470909681),
        IVF(5840696475078001361), IVF(11170449401992604703),
        IVF(2270897969802886507), IVF(6620516959819538809)
    };

    // Column-S3 per-q quadratic constants from tx = tanh(5*IV[4+q]-2.5),
    // scale 2^-32 folded in. (tanha error here lands *2^-32 -> invisible.)
    float A3[4], B3[4], C3[4];
#pragma unroll
    for (int q = 0; q < 4; q++) {
        float txc = tanha(fmaf(IVf[4 + q], 5.0f, -2.5f));
        float Dq  = fmaf(-txc, txc, 1.0f) * 0.0625f;
        A3[q] = (0.5f - Dq) * 0x1p-32f;
        B3[q] = (-0.5f * txc) * 0x1p-32f;
        C3[q] = Dq * 0x1p-32f;
    }

    float m[16];
    {
        const float4* mp = reinterpret_cast<const float4*>(msg) + (size_t)i * 4;
        float4 q0 = mp[0], q1 = mp[1], q2 = mp[2], q3 = mp[3];
        m[0] = q0.x;  m[1] = q0.y;  m[2] = q0.z;  m[3] = q0.w;
        m[4] = q1.x;  m[5] = q1.y;  m[6] = q1.z;  m[7] = q1.w;
        m[8] = q2.x;  m[9] = q2.y;  m[10] = q2.z; m[11] = q2.w;
        m[12] = q3.x; m[13] = q3.y; m[14] = q3.z; m[15] = q3.w;
    }

    float v[16];
#pragma unroll
    for (int j = 0; j < 8; j++) v[j] = IVf[j];

#define IA(q) (q)
#define IB(q) (DIAG ? 4 + (((q) + 1) & 3) : 4 + (q))
#define IC(q) (DIAG ? 8 + (((q) + 2) & 3) : 8 + (q))
#define ID(q) (DIAG ? 12 + (((q) + 3) & 3) : 12 + (q))
#define IX(q) (DIAG ? 8 + 2 * (q) : 2 * (q))
#define IY(q) (DIAG ? 9 + 2 * (q) : 2 * (q) + 1)

// soft_add over 4 lanes: s = v+u; g = sigmoid(10(s-1)); v = s-g
#define SA4(TIDX, UEXPR)                                                      \
    {                                                                         \
        float s_[4], w_[4], g_[4];                                            \
        _Pragma("unroll") for (int q = 0; q < 4; q++) s_[q] = v[TIDX] + (UEXPR); \
        _Pragma("unroll") for (int q = 0; q < 4; q++) w_[q] = fmaf(s_[q], -K10, K10); \
        sigb4<false>(w_, g_);                                                 \
        _Pragma("unroll") for (int q = 0; q < 4; q++) v[TIDX] = s_[q] - g_[q]; \
    }

#define G4BODY()                                                              \
    {                                                                         \
        /* S1: a = sa(a, b) */                                                \
        SA4(IA(q), v[IB(q)]);                                                 \
        /* S2: a = sa(a, m[x]) */                                             \
        SA4(IA(q), m[IX(q)]);                                                 \
        /* S3: d = sx(d_const, a) * 2^-32 : quadratic in ty */                \
        _Pragma("unroll") for (int q = 0; q < 4; q++) {                       \
            float ty = tanha(fmaf(v[IA(q)], 5.0f, -2.5f));                    \
            float tA = DIAG ? A32 : A3[q];                                    \
            float tB = DIAG ? B32 : B3[q];                                    \
            float tC = DIAG ? C32 : C3[q];                                    \
            float t0 = fmaf(ty, tB, tA);                                      \
            v[ID(q)] = fmaf(ty * ty, tC, t0);                                 \
        }                                                                     \
        /* S4: c = sa(c, d) */                                                \
        SA4(IC(q), v[ID(q)]);                                                 \
        /* S5: b = sx(b, c) * 2^-24 (full tanh form, scale folded) */         \
        _Pragma("unroll") for (int q = 0; q < 4; q++) {                       \
            float tx = tanha(fmaf(v[IB(q)], 5.0f, -2.5f));                    \
            float ty = tanha(fmaf(v[IC(q)], 5.0f, -2.5f));                    \
            float p  = tx * ty;                                               \
            float a0 = fmaf(p, -0x1p-25f, 0x1p-25f);                          \
            float q1 = fmaf(-tx, tx, 1.0f);                                   \
            float q2 = fmaf(-ty, ty, 1.0f);                                   \
            v[IB(q)] = fmaf(q1 * q2, -0x1p-28f, a0);                          \
        }                                                                     \
        /* S6: a = sa(a, b) */                                                \
        SA4(IA(q), v[IB(q)]);                                                 \
        /* S7: a = sa(a, m[y]) */                                             \
        SA4(IA(q), m[IY(q)]);                                                 \
        /* S8: d = sx(d_tiny, a) * 2^-16 : quadratic in ty, global consts */  \
        _Pragma("unroll") for (int q = 0; q < 4; q++) {                       \
            float ty = tanha(fmaf(v[IA(q)], 5.0f, -2.5f));                    \
            float t0 = fmaf(ty, B16, A16);                                    \
            v[ID(q)] = fmaf(ty * ty, C16, t0);                                \
        }                                                                     \
        /* S9: c = sa(c, d) */                                                \
        SA4(IC(q), v[ID(q)]);                                                 \
        /* S10: b = rot63(sx(xs_const, ys)) : quadratic in ys + exact rot */  \
        {                                                                     \
            float wy_[4], ys_[4];                                             \
            _Pragma("unroll") for (int q = 0; q < 4; q++)                     \
                wy_[q] = fmaf(v[IC(q)], -K10, KH);                            \
            sigb4<true>(wy_, ys_);                                            \
            _Pragma("unroll") for (int q = 0; q < 4; q++) {                   \
                float ys = ys_[q];                                            \
                float t0 = fmaf(ys, S10B, S10A);                              \
                float f  = __saturatef(fmaf(ys * ys, S10G, t0));              \
                v[IB(q)] = rot63f(f);                                         \
            }                                                                 \
        }                                                                     \
    }

#pragma unroll 1
    for (int r = 0; r < 10; r++) {
#pragma unroll
        for (int j = 0; j < 8; j++) v[8 + j] = IVf[j];

        { constexpr bool DIAG = false; G4BODY(); }   // column: 4 independent G
        { constexpr bool DIAG = true;  G4BODY(); }   // diagonal: 4 independent G

        // state = soft_xor(v[j], v[8+j])
        {
            float wx[4], xs[4], wy[4], ys[4];
#pragma unroll
            for (int j = 0; j < 4; j++) {
                wx[j] = fmaf(v[j],     -K10, KH);
                wy[j] = fmaf(v[8 + j], -K10, KH);
            }
            sigb4<true>(wx, xs);
            sigb4<true>(wy, ys);
#pragma unroll
            for (int j = 0; j < 4; j++) v[j] = xorcomb(xs[j], ys[j]);
        }
        {
            // j=4..7: v[8+j] is rot16-out (<=7.8e-6): linear sigmoid exact
            float wx[4], xs[4];
#pragma unroll
            for (int j = 0; j < 4; j++) wx[j] = fmaf(v[4 + j], -K10, KH);
            sigb4<true>(wx, xs);
#pragma unroll
            for (int j = 0; j < 4; j++) {
                float ysl = fmaf(v[12 + j], SIG5S, SIG5);
                v[4 + j] = xorcomb(xs[j], ysl);
            }
        }
    }

    float4* op = reinterpret_cast<float4*>(out) + (size_t)i * 2;
    op[0] = make_float4(v[0], v[1], v[2], v[3]);
    op[1] = make_float4(v[4], v[5], v[6], v[7]);
}

extern "C" void kernel_launch(void* const* d_in, const int* in_sizes, int n_in,
                              void* d_out, int out_size) {
    const float* msg = (const float*)d_in[0];
    float* out = (float*)d_out;
    int batch = in_sizes[0] / 16;
    int blocks = (batch + 127) / 128;
    blake2_soft_kernel<<<blocks, 128>>>(msg, out, batch);
}

// round 10
// speedup vs baseline: 1.7977x; 1.4575x over previous
#include <cuda_runtime.h>
#include <cstdint>

// ---------------------------------------------------------------------------
// Blake2Cipher soft-hash, fp32 — R9: c-channel affine folding.
// Words 8..11 (c) start at IV each round and receive only tiny (<=2^-16)
// increments -> their whole round trajectory is constant + affine terms.
// S3 stages are dead in reference fp32 arithmetic (outputs round away).
// MUFU/round: 117 -> 66.
// ---------------------------------------------------------------------------

__device__ __forceinline__ float ex2a(float x){ float r; asm("ex2.approx.f32 %0, %1;" : "=f"(r) : "f"(x)); return r; }
__device__ __forceinline__ float rcpa(float x){ float r; asm("rcp.approx.f32 %0, %1;" : "=f"(r) : "f"(x)); return r; }
__device__ __forceinline__ float tanha(float x){ float r; asm("tanh.approx.f32 %0, %1;" : "=f"(r) : "f"(x)); return r; }

#define K10   14.42695041f    // 10*log2(e)
#define KH     7.213475205f   // 5*log2(e)
#define SIG5   0.0066928509f  // sigmoid(-5)
#define SIG5S  0.066480567f   // d/dx sigmoid(10x-5) at x=0
#define TH25   0.98661430f    // tanh(2.5)

// S8 fold: tx = -TH25 const (d-input ~2^-32), scale 2^-16 folded.
#define DQC   ((1.0f - TH25*TH25) * 0.0625f)
#define A16   ((0.5f - DQC) * 0x1p-16f)
#define B16   ((0.5f * TH25) * 0x1p-16f)
#define C16   (DQC * 0x1p-16f)

// S10 soft_xor with xs = SIG5 const: f = S10A + S10B*ys + S10G*ys^2
#define S10A  (SIG5)
#define S10B  ((1.0f - 2.0f*SIG5) - SIG5*(1.0f - SIG5))
#define S10G  (SIG5*(1.0f - SIG5))

// Accurate sigmoid for prologue constants (matches baseline noise ~1e-7).
__device__ __forceinline__ float sigm1(float z) {
    float e = __expf(-z);
    return __fdividef(1.0f, 1.0f + e);
}

// batch-4 sigmoid; w = -z*log2(e); g = 1/(1+2^w); optional Newton refine.
template <bool NR>
__device__ __forceinline__ void sigb4(const float w[4], float g[4]) {
    float d0 = 1.0f + ex2a(w[0]);
    float d1 = 1.0f + ex2a(w[1]);
    float d2 = 1.0f + ex2a(w[2]);
    float d3 = 1.0f + ex2a(w[3]);
    float p01 = d0 * d1, p23 = d2 * d3;
    float P = p01 * p23;
    float R = rcpa(P);
    if (NR) {
        float er = fmaf(-P, R, 1.0f);
        R = fmaf(R, er, R);
    }
    float R01 = R * p23, R23 = R * p01;
    g[0] = R01 * d1; g[1] = R01 * d0;
    g[2] = R23 * d3; g[3] = R23 * d2;
}

// Exact rot63: f in [0,1] -> 2f (f<0.5) or 2f-1 (f>=0.5).
__device__ __forceinline__ float rot63f(float f) {
    float t = f + f;
    float r = t - 1.0f;
    return (t >= 1.0f) ? r : t;
}

// Clamped soft_xor combine from precomputed sigmoids.
__device__ __forceinline__ float xorcomb(float xs, float ys) {
    float p = xs * ys;
    float s = xs + ys;
    float u = fmaf(p, -2.0f, s);      // t1+t2
    float q = (1.0f + p) - s;         // (1-xs)(1-ys)
    return __saturatef(fmaf(-p, q, u));
}

#define IVF(x) ((float)(x##ull) * 0x1p-64f)

__global__ void __launch_bounds__(128, 5)
blake2_soft_kernel(const float* __restrict__ msg, float* __restrict__ out, int batch) {
    int i = blockIdx.x * 128 + threadIdx.x;
    if (i >= batch) return;

    const float IVf[8] = {
        IVF(7640891576956012808), IVF(13503953896175478587),
        IVF(4354685564936845355), IVF(11912009170470909681),
        IVF(5840696475078001361), IVF(11170449401992604703),
        IVF(2270897969802886507), IVF(6620516959819538809)
    };

    // -------- prologue: c-channel constants per column lane q --------
    // Runtime per q: A5,B5,C5 (col-S5 quad), F0,F1,F2 (col-S10 quad in d16c),
    // t0,TS1 (diag-S5 ty affine), H1 (u' compose), yd0,YS1 (diag-S10 ys affine)
    float A5[4], B5[4], C5[4], F0[4], F1[4], F2[4];
    float T0c[4], TS1[4], H1[4], YD0[4], YS1[4];
#pragma unroll
    for (int q = 0; q < 4; q++) {
        float IVq = IVf[q];
        // col-S4: c1 = IVq - sigma(10(IVq-1))  [exact constant]
        float sA  = sigm1(10.0f * (IVq - 1.0f));
        float CA1 = IVq - sA;
        // col-S5 ty const (protected by 2^-24 -> tanha ok)
        float ty5 = tanha(fmaf(CA1, 5.0f, -2.5f));
        float E5  = fmaf(-ty5, ty5, 1.0f) * 0.0625f;
        A5[q] = (0.5f - E5) * 0x1p-24f;
        B5[q] = (-0.5f * ty5) * 0x1p-24f;
        C5[q] = E5 * 0x1p-24f;
        // col-S9 affine: c2 = CA2 + S2c * d16c
        float s9  = sigm1(10.0f * (CA1 - 1.0f));
        float CA2 = CA1 - s9;
        float S2c = fmaf(-10.0f * s9, (1.0f - s9), 1.0f);
        // col-S10: ys = y0 + Y1c*d16c ; f = S10A+S10B ys+S10G ys^2
        //   pre-expand in d16c: f = F0 + F1*d + F2*d^2
        float y0  = sigm1(10.0f * (CA2 - 0.5f));
        float Y1c = 10.0f * y0 * (1.0f - y0) * S2c;
        F0[q] = fmaf(y0, S10B, S10A) + y0 * y0 * S10G;
        F1[q] = fmaf(2.0f * S10G, y0, S10B) * Y1c;
        F2[q] = S10G * Y1c * Y1c;
        // diag-S4 affine: c3 = CB1 + G1*(S2c*d16c)   (d32 rounds away)
        float sb  = sigm1(10.0f * (CA2 - 1.0f));
        float CB1 = CA2 - sb;
        float G1  = fmaf(-10.0f * sb, (1.0f - sb), 1.0f);
        // diag-S5 ty affine (protected by 2^-24)
        float t0  = tanha(fmaf(CB1, 5.0f, -2.5f));
        T0c[q] = t0;
        TS1[q] = 5.0f * fmaf(-t0, t0, 1.0f) * G1 * S2c;
        // diag-S9 affine: c4 = CB2 + G2*w, w = H1*d16c + d16d
        float sc  = sigm1(10.0f * (CB1 - 1.0f));
        float CB2 = CB1 - sc;
        float G2  = fmaf(-10.0f * sc, (1.0f - sc), 1.0f);
        H1[q] = G1 * S2c;
        // diag-S10 / final-xor ys: ys = yd0 + YS1*w
        float yd0 = sigm1(10.0f * (CB2 - 0.5f));
        YD0[q] = yd0;
        YS1[q] = 10.0f * yd0 * (1.0f - yd0) * G2;
    }

    // -------- load message --------
    float m[16];
    {
        const float4* mp = reinterpret_cast<const float4*>(msg) + (size_t)i * 4;
        float4 q0 = mp[0], q1 = mp[1], q2 = mp[2], q3 = mp[3];
        m[0] = q0.x;  m[1] = q0.y;  m[2] = q0.z;  m[3] = q0.w;
        m[4] = q1.x;  m[5] = q1.y;  m[6] = q1.z;  m[7] = q1.w;
        m[8] = q2.x;  m[9] = q2.y;  m[10] = q2.z; m[11] = q2.w;
        m[12] = q3.x; m[13] = q3.y; m[14] = q3.z; m[15] = q3.w;
    }

    // Live state: a-words v[0..3], b-words v[4..7]. (c,d folded.)
    float v[8];
#pragma unroll
    for (int j = 0; j < 8; j++) v[j] = IVf[j];

// soft_add batch over the 4 a-words: v[q] = sa(v[q], ADDEND)
#define SA4(ADDEND)                                                           \
    {                                                                         \
        float s_[4], w_[4], g_[4];                                            \
        _Pragma("unroll") for (int q = 0; q < 4; q++) s_[q] = v[q] + (ADDEND); \
        _Pragma("unroll") for (int q = 0; q < 4; q++) w_[q] = fmaf(s_[q], -K10, K10); \
        sigb4<false>(w_, g_);                                                 \
        _Pragma("unroll") for (int q = 0; q < 4; q++) v[q] = s_[q] - g_[q];   \
    }

#pragma unroll 1
    for (int r = 0; r < 10; r++) {
        float d16c[4], d16d[4], ysd[4];

        // ================= column step (lanes q: a=v[q], b=v[4+q]) =========
        SA4(v[4 + q]);          // S1
        SA4(m[2 * q]);          // S2
        // (S3 dead, S4 constant)
        // S5: b24 = sx(b, c1_const) * 2^-24  — quadratic in tx
        float b24[4];
#pragma unroll
        for (int q = 0; q < 4; q++) {
            float tx = tanha(fmaf(v[4 + q], 5.0f, -2.5f));
            float t0_ = fmaf(tx, B5[q], A5[q]);
            b24[q] = fmaf(tx * tx, C5[q], t0_);
        }
        SA4(b24[q]);            // S6
        SA4(m[2 * q + 1]);      // S7
        // S8: d16c = sx(d_tiny, a) * 2^-16 — quadratic in ty
#pragma unroll
        for (int q = 0; q < 4; q++) {
            float ty = tanha(fmaf(v[q], 5.0f, -2.5f));
            float t0_ = fmaf(ty, B16, A16);
            d16c[q] = fmaf(ty * ty, C16, t0_);
        }
        // (S9 affine-folded into F/H constants)
        // S10: f = F0 + F1*d + F2*d^2 ; b = rot63(clamp(f))
#pragma unroll
        for (int q = 0; q < 4; q++) {
            float d = d16c[q];
            float f = __saturatef(fmaf(fmaf(F2[q], d, F1[q]), d, F0[q]));
            v[4 + q] = rot63f(f);
        }

        // ================= diagonal step (lane q: a=v[q], b=v[4+((q+1)&3)],
        //                   c-channel qc=(q+2)&3, d-in channel (q+3)&3) =====
        SA4(v[4 + ((q + 1) & 3)]);   // S1
        SA4(m[8 + 2 * q]);           // S2
        // (S3 dead, S4 affine)
        // S5: ty affine in d16c[qc]; tx = tanh(b); scale 2^-24 folded
        float b24d[4];
#pragma unroll
        for (int q = 0; q < 4; q++) {
            int qc = (q + 2) & 3;
            float tx = tanha(fmaf(v[4 + ((q + 1) & 3)], 5.0f, -2.5f));
            float ty = fmaf(d16c[qc], TS1[qc], T0c[qc]);
            float p  = tx * ty;
            float a0 = fmaf(p, -0x1p-25f, 0x1p-25f);
            float q1 = fmaf(-tx, tx, 1.0f);
            float q2 = fmaf(-ty, ty, 1.0f);
            b24d[q] = fmaf(q1 * q2, -0x1p-28f, a0);
        }
        SA4(b24d[q]);                // S6
        SA4(m[9 + 2 * q]);           // S7
        // S8: d16d = quadratic in ty(a)
#pragma unroll
        for (int q = 0; q < 4; q++) {
            float ty = tanha(fmaf(v[q], 5.0f, -2.5f));
            float t0_ = fmaf(ty, B16, A16);
            d16d[q] = fmaf(ty * ty, C16, t0_);
        }
        // (S9 affine) S10: w = H1*d16c + d16d ; ys = yd0 + YS1*w ;
        //             f = S10A + S10B ys + S10G ys^2 ; b = rot63(clamp(f))
#pragma unroll
        for (int q = 0; q < 4; q++) {
            int qc = (q + 2) & 3;
            float w  = fmaf(H1[qc], d16c[qc], d16d[q]);
            float ys = fmaf(YS1[qc], w, YD0[qc]);
            ysd[q]   = ys;
            float t0_ = fmaf(ys, S10B, S10A);
            float f  = __saturatef(fmaf(ys * ys, S10G, t0_));
            v[4 + ((q + 1) & 3)] = rot63f(f);
        }

        // ================= final state xor ==================================
        // j=0..3: state = sx(v[j], c4_word_j); ys of word 8+j == ysd[(j+2)&3]
        {
            float wx[4], xs[4];
#pragma unroll
            for (int j = 0; j < 4; j++) wx[j] = fmaf(v[j], -K10, KH);
            sigb4<true>(wx, xs);
#pragma unroll
            for (int j = 0; j < 4; j++) v[j] = xorcomb(xs[j], ysd[(j + 2) & 3]);
        }
        // j=4..7: state = sx(v[j], d_word); d word 12+k = d16d[(k+1)&3] (tiny)
        {
            float wx[4], xs[4];
#pragma unroll
            for (int k = 0; k < 4; k++) wx[k] = fmaf(v[4 + k], -K10, KH);
            sigb4<true>(wx, xs);
#pragma unroll
            for (int k = 0; k < 4; k++) {
                float ysl = fmaf(d16d[(k + 1) & 3], SIG5S, SIG5);
                v[4 + k] = xorcomb(xs[k], ysl);
            }
        }
    }

    float4* op = reinterpret_cast<float4*>(out) + (size_t)i * 2;
    op[0] = make_float4(v[0], v[1], v[2], v[3]);
    op[1] = make_float4(v[4], v[5], v[6], v[7]);
}

extern "C" void kernel_launch(void* const* d_in, const int* in_sizes, int n_in,
                              void* d_out, int out_size) {
    const float* msg = (const float*)d_in[0];
    float* out = (float*)d_out;
    int batch = in_sizes[0] / 16;
    int blocks = (batch + 127) / 128;
    blake2_soft_kernel<<<blocks, 128>>>(msg, out, batch);
}

// round 11
// speedup vs baseline: 1.8894x; 1.0510x over previous
#include <cuda_runtime.h>
#include <cstdint>

// ---------------------------------------------------------------------------
// Blake2Cipher soft-hash, fp32 — R11: c-channel + b-channel folding.
// Adds to R9: diag-S5 collapsed to affine (b, d16c); final-xor j=4..7
// collapsed to polynomials (xs quadratic in b, ysl expansion exact);
// F2/clamps dropped (provably interior). MUFU/round 66 -> 57.
// ---------------------------------------------------------------------------

__device__ __forceinline__ float ex2a(float x){ float r; asm("ex2.approx.f32 %0, %1;" : "=f"(r) : "f"(x)); return r; }
__device__ __forceinline__ float rcpa(float x){ float r; asm("rcp.approx.f32 %0, %1;" : "=f"(r) : "f"(x)); return r; }
__device__ __forceinline__ float tanha(float x){ float r; asm("tanh.approx.f32 %0, %1;" : "=f"(r) : "f"(x)); return r; }

#define K10   14.42695041f    // 10*log2(e)
#define KH     7.213475205f   // 5*log2(e)
#define SIG5   0.0066928509f  // sigmoid(-5)
#define SIG5S  0.066480567f   // d/dx sigmoid(10x-5) at x=0
#define TH25   0.98661430f    // tanh(2.5)

// S8 fold: tx = -TH25 const (d-input ~2^-32), scale 2^-16 folded.
#define DQC   ((1.0f - TH25*TH25) * 0.0625f)
#define A16   ((0.5f - DQC) * 0x1p-16f)
#define B16   ((0.5f * TH25) * 0x1p-16f)
#define C16   (DQC * 0x1p-16f)

// S10 soft_xor with xs = SIG5 const: f = S10A + S10B*ys + S10G*ys^2
#define S10A  (SIG5)
#define S10B  ((1.0f - 2.0f*SIG5) - SIG5*(1.0f - SIG5))
#define S10G  (SIG5*(1.0f - SIG5))

// final-B xor expansion: f = SIG5 + xs*FB_A1 + xs^2*FB_A2
//                          + d16d*(FB_B0 + xs*FB_B1 + xs^2*FB_B2)
#define FB_A1 (1.0f - 3.0f*SIG5 + SIG5*SIG5)
#define FB_A2 (SIG5 - SIG5*SIG5)
#define FB_B0 (SIG5S)
#define FB_B1 (SIG5S*(2.0f*SIG5 - 3.0f))
#define FB_B2 (SIG5S*(1.0f - 2.0f*SIG5))

// Accurate sigmoid for prologue constants.
__device__ __forceinline__ float sigm1(float z) {
    float e = __expf(-z);
    return __fdividef(1.0f, 1.0f + e);
}
__device__ __forceinline__ float tanh_acc(float z) {
    return fmaf(2.0f, sigm1(2.0f * z), -1.0f);
}

// batch-4 sigmoid; w = -z*log2(e); g = 1/(1+2^w).
template <bool NR>
__device__ __forceinline__ void sigb4(const float w[4], float g[4]) {
    float d0 = 1.0f + ex2a(w[0]);
    float d1 = 1.0f + ex2a(w[1]);
    float d2 = 1.0f + ex2a(w[2]);
    float d3 = 1.0f + ex2a(w[3]);
    float p01 = d0 * d1, p23 = d2 * d3;
    float P = p01 * p23;
    float R = rcpa(P);
    if (NR) {
        float er = fmaf(-P, R, 1.0f);
        R = fmaf(R, er, R);
    }
    float R01 = R * p23, R23 = R * p01;
    g[0] = R01 * d1; g[1] = R01 * d0;
    g[2] = R23 * d3; g[3] = R23 * d2;
}

// Exact rot63: f in (0,1) -> 2f (f<0.5) or 2f-1 (f>=0.5).
__device__ __forceinline__ float rot63f(float f) {
    float t = f + f;
    float r = t - 1.0f;
    return (t >= 1.0f) ? r : t;
}

// Clamped soft_xor combine from precomputed sigmoids (final-A only).
__device__ __forceinline__ float xorcomb(float xs, float ys) {
    float p = xs * ys;
    float s = xs + ys;
    float u = fmaf(p, -2.0f, s);      // t1+t2
    float q = (1.0f + p) - s;         // (1-xs)(1-ys)
    return __saturatef(fmaf(-p, q, u));
}

#define IVF(x) ((float)(x##ull) * 0x1p-64f)

__global__ void __launch_bounds__(128, 5)
blake2_soft_kernel(const float* __restrict__ msg, float* __restrict__ out, int batch) {
    int i = blockIdx.x * 128 + threadIdx.x;
    if (i >= batch) return;

    const float IVf[8] = {
        IVF(7640891576956012808), IVF(13503953896175478587),
        IVF(4354685564936845355), IVF(11912009170470909681),
        IVF(5840696475078001361), IVF(11170449401992604703),
        IVF(2270897969802886507), IVF(6620516959819538809)
    };

    // ---------------- prologue pass 1: c-channel trajectory per lane q -----
    float A5[4], B5[4], C5[4];           // col-S5 quad coeffs (tanha tx)
    float F0[4], F1[4];                  // col-S10 affine in d16c
    float H1v[4], YD0v[4], YS1v[4];      // diag-S9/S10 affine
    float T0cv[4], TS1v[4];              // diag-S5 ty affine
    float BCv[4];                        // base of col-S10 output
#pragma unroll
    for (int q = 0; q < 4; q++) {
        float IVq = IVf[q];
        float sA  = sigm1(10.0f * (IVq - 1.0f));
        float CA1 = IVq - sA;
        // col-S5 ty const (from c1 = CA1), scale 2^-24 folded
        float ty5 = tanh_acc(fmaf(CA1, 5.0f, -2.5f));
        float E5  = fmaf(-ty5, ty5, 1.0f) * 0.0625f;
        A5[q] = (0.5f - E5) * 0x1p-24f;
        B5[q] = (-0.5f * ty5) * 0x1p-24f;
        C5[q] = E5 * 0x1p-24f;
        // col-S9 affine
        float s9  = sigm1(10.0f * (CA1 - 1.0f));
        float CA2 = CA1 - s9;
        float S2c = fmaf(-10.0f * s9, (1.0f - s9), 1.0f);
        // col-S10 quad -> affine (F2 term ~1e-11, dropped)
        float y0  = sigm1(10.0f * (CA2 - 0.5f));
        float Y1c = 10.0f * y0 * (1.0f - y0) * S2c;
        F0[q] = fmaf(y0, S10B, S10A) + y0 * y0 * S10G;
        F1[q] = fmaf(2.0f * S10G, y0, S10B) * Y1c;
        BCv[q] = rot63f(F0[q]);
        // diag-S4 affine
        float sb  = sigm1(10.0f * (CA2 - 1.0f));
        float CB1 = CA2 - sb;
        float G1  = fmaf(-10.0f * sb, (1.0f - sb), 1.0f);
        // diag-S5 ty affine
        float t0  = tanh_acc(fmaf(CB1, 5.0f, -2.5f));
        T0cv[q] = t0;
        TS1v[q] = 5.0f * fmaf(-t0, t0, 1.0f) * G1 * S2c;
        // diag-S9 affine
        float sc  = sigm1(10.0f * (CB1 - 1.0f));
        float CB2 = CB1 - sc;
        float G2  = fmaf(-10.0f * sc, (1.0f - sc), 1.0f);
        H1v[q] = G1 * S2c;
        float yd0 = sigm1(10.0f * (CB2 - 0.5f));
        YD0v[q] = yd0;
        YS1v[q] = 10.0f * yd0 * (1.0f - yd0) * G2;
    }

    // ---------------- prologue pass 2: b-channel fold coefficients ---------
    float E0[4], E1[4], E2[4];           // diag-S5: b24d = E0 + E1*b + E2*d16c[qc]
    float P0[4], P1[4], P2[4];           // final-B: xs = P0 + P1*b + P2*b^2
#pragma unroll
    for (int q = 0; q < 4; q++) {
        int kb = (q + 1) & 3, qc = (q + 2) & 3;
        // diag-S5 fold around (TXd, ty0)
        float TXd = tanh_acc(fmaf(BCv[kb], 5.0f, -2.5f));
        float ty0 = T0cv[qc];
        float omx = fmaf(-TXd, TXd, 1.0f);     // 1 - TXd^2
        float omy = fmaf(-ty0, ty0, 1.0f);     // 1 - ty0^2
        float S0  = 0.5f - 0.5f * TXd * ty0 - omx * omy * 0.0625f;
        float dsx = fmaf(TXd, omy * 0.125f, -0.5f * ty0);
        float dsy = fmaf(ty0, omx * 0.125f, -0.5f * TXd);
        E1[q] = 0x1p-24f * dsx * (5.0f * omx);
        E2[q] = 0x1p-24f * dsy * TS1v[qc];
        E0[q] = fmaf(-E1[q], BCv[kb], 0x1p-24f * S0);
        // final-B fold: word 4+q written by diag lane (q+3)&3, ys lane (q+1)&3
        float ydw = YD0v[(q + 1) & 3];
        float fd0 = fmaf(ydw, S10B, S10A) + ydw * ydw * S10G;
        float BW  = rot63f(fd0);
        float xv  = sigm1(10.0f * (BW - 0.5f));
        float xss = 10.0f * xv * (1.0f - xv);
        float xsc = 50.0f * xv * (1.0f - xv) * (1.0f - 2.0f * xv);  // (1/2)*d2xs/db2
        // expand xv + xss*(b-BW) + xsc*(b-BW)^2 in powers of b
        P2[q] = xsc;
        P1[q] = fmaf(-2.0f * xsc, BW, xss);
        P0[q] = fmaf(fmaf(xsc, BW, -xss), BW, xv);
    }

    // -------- load message --------
    float m[16];
    {
        const float4* mp = reinterpret_cast<const float4*>(msg) + (size_t)i * 4;
        float4 q0 = mp[0], q1 = mp[1], q2 = mp[2], q3 = mp[3];
        m[0] = q0.x;  m[1] = q0.y;  m[2] = q0.z;  m[3] = q0.w;
        m[4] = q1.x;  m[5] = q1.y;  m[6] = q1.z;  m[7] = q1.w;
        m[8] = q2.x;  m[9] = q2.y;  m[10] = q2.z; m[11] = q2.w;
        m[12] = q3.x; m[13] = q3.y; m[14] = q3.z; m[15] = q3.w;
    }

    // Live state: a-words v[0..3], b-words v[4..7].
    float v[8];
#pragma unroll
    for (int j = 0; j < 8; j++) v[j] = IVf[j];

#define SA4(ADDEND)                                                           \
    {                                                                         \
        float s_[4], w_[4], g_[4];                                            \
        _Pragma("unroll") for (int q = 0; q < 4; q++) s_[q] = v[q] + (ADDEND); \
        _Pragma("unroll") for (int q = 0; q < 4; q++) w_[q] = fmaf(s_[q], -K10, K10); \
        sigb4<false>(w_, g_);                                                 \
        _Pragma("unroll") for (int q = 0; q < 4; q++) v[q] = s_[q] - g_[q];   \
    }

#pragma unroll 1
    for (int r = 0; r < 10; r++) {
        float d16c[4], d16d[4], ysd[4];

        // ================= column step =====================================
        SA4(v[4 + q]);          // S1
        SA4(m[2 * q]);          // S2
        // S5: b24 = quad(tanh(5b-2.5)) — b is prev state word, data-dep
        float b24[4];
#pragma unroll
        for (int q = 0; q < 4; q++) {
            float tx = tanha(fmaf(v[4 + q], 5.0f, -2.5f));
            float t0_ = fmaf(tx, B5[q], A5[q]);
            b24[q] = fmaf(tx * tx, C5[q], t0_);
        }
        SA4(b24[q]);            // S6
        SA4(m[2 * q + 1]);      // S7
        // S8: d16c = quad(tanh(5a-2.5))
#pragma unroll
        for (int q = 0; q < 4; q++) {
            float ty = tanha(fmaf(v[q], 5.0f, -2.5f));
            float t0_ = fmaf(ty, B16, A16);
            d16c[q] = fmaf(ty * ty, C16, t0_);
        }
        // S10: b = rot63f(F0 + F1*d16c)  (interior; no clamp)
#pragma unroll
        for (int q = 0; q < 4; q++)
            v[4 + q] = rot63f(fmaf(d16c[q], F1[q], F0[q]));

        // ================= diagonal step ===================================
        SA4(v[4 + ((q + 1) & 3)]);   // S1
        SA4(m[8 + 2 * q]);           // S2
        // S5: b24d affine in (b, d16c[qc]) — b = col-S10 out (near BC base)
        float b24d[4];
#pragma unroll
        for (int q = 0; q < 4; q++) {
            float b = v[4 + ((q + 1) & 3)];
            b24d[q] = fmaf(d16c[(q + 2) & 3], E2[q], fmaf(b, E1[q], E0[q]));
        }
        SA4(b24d[q]);                // S6
        SA4(m[9 + 2 * q]);           // S7
        // S8: d16d = quad(tanh(5a-2.5))
#pragma unroll
        for (int q = 0; q < 4; q++) {
            float ty = tanha(fmaf(v[q], 5.0f, -2.5f));
            float t0_ = fmaf(ty, B16, A16);
            d16d[q] = fmaf(ty * ty, C16, t0_);
        }
        // S10: w = H1*d16c + d16d ; ys = YD0 + YS1*w ; f quad; b = rot63f(f)
#pragma unroll
        for (int q = 0; q < 4; q++) {
            int qc = (q + 2) & 3;
            float w  = fmaf(H1v[qc], d16c[qc], d16d[q]);
            float ys = fmaf(YS1v[qc], w, YD0v[qc]);
            ysd[q]   = ys;
            float f  = fmaf(ys, fmaf(ys, S10G, S10B), S10A);
            v[4 + ((q + 1) & 3)] = rot63f(f);
        }

        // ================= final state xor =================================
        // j=0..3: xs = sigma(10(a-0.5)) batch; ys = ysd[(j+2)&3]
        {
            float wx[4], xs[4];
#pragma unroll
            for (int j = 0; j < 4; j++) wx[j] = fmaf(v[j], -K10, KH);
            sigb4<true>(wx, xs);
#pragma unroll
            for (int j = 0; j < 4; j++) v[j] = xorcomb(xs[j], ysd[(j + 2) & 3]);
        }
        // j=4..7: xs quadratic in b (b = diag-S10 out, near BW base);
        //         xor with ysl = SIG5 + SIG5S*d16d' expanded exactly.
#pragma unroll
        for (int k = 0; k < 4; k++) {
            float b  = v[4 + k];
            float xs = fmaf(b, fmaf(b, P2[k], P1[k]), P0[k]);
            float f0 = fmaf(xs, fmaf(xs, FB_A2, FB_A1), SIG5);
            float g  = fmaf(xs, fmaf(xs, FB_B2, FB_B1), FB_B0);
            v[4 + k] = fmaf(d16d[(k + 1) & 3], g, f0);
        }
    }

    float4* op = reinterpret_cast<float4*>(out) + (size_t)i * 2;
    op[0] = make_float4(v[0], v[1], v[2], v[3]);
    op[1] = make_float4(v[4], v[5], v[6], v[7]);
}

extern "C" void kernel_launch(void* const* d_in, const int* in_sizes, int n_in,
                              void* d_out, int out_size) {
    const float* msg = (const float*)d_in[0];
    float* out = (float*)d_out;
    int batch = in_sizes[0] / 16;
    int blocks = (batch + 127) / 128;
    blake2_soft_kernel<<<blocks, 128>>>(msg, out, batch);
}

// round 12
// speedup vs baseline: 1.9547x; 1.0345x over previous
#include <cuda_runtime.h>
#include <cstdint>

// ---------------------------------------------------------------------------
// Blake2Cipher soft-hash, fp32 — R12: c+b-channel folds + tanh-from-xs.
//  * diag-S8 ty = 2*xs-1 (exact identity with final-A sigmoid batch).
//  * col-S5 quadratic in b (state-B words near-constant, base Bst); r=0 uses
//    exact IV-based constants.
//  * SA4 epilogue fused to FFMA; final-A batch without Newton refine.
// MUFU/round 57 -> 49.
// ---------------------------------------------------------------------------

__device__ __forceinline__ float ex2a(float x){ float r; asm("ex2.approx.f32 %0, %1;" : "=f"(r) : "f"(x)); return r; }
__device__ __forceinline__ float rcpa(float x){ float r; asm("rcp.approx.f32 %0, %1;" : "=f"(r) : "f"(x)); return r; }
__device__ __forceinline__ float tanha(float x){ float r; asm("tanh.approx.f32 %0, %1;" : "=f"(r) : "f"(x)); return r; }

#define K10   14.42695041f    // 10*log2(e)
#define KH     7.213475205f   // 5*log2(e)
#define SIG5   0.0066928509f  // sigmoid(-5)
#define SIG5S  0.066480567f   // d/dx sigmoid(10x-5) at x=0
#define TH25   0.98661430f    // tanh(2.5)

// S8 fold: tx = -TH25 const, scale 2^-16 folded.
#define DQC   ((1.0f - TH25*TH25) * 0.0625f)
#define A16   ((0.5f - DQC) * 0x1p-16f)
#define B16   ((0.5f * TH25) * 0x1p-16f)
#define C16   (DQC * 0x1p-16f)

// S10 soft_xor with xs = SIG5 const: f = S10A + S10B*ys + S10G*ys^2
#define S10A  (SIG5)
#define S10B  ((1.0f - 2.0f*SIG5) - SIG5*(1.0f - SIG5))
#define S10G  (SIG5*(1.0f - SIG5))

// final-B xor expansion
#define FB_A1 (1.0f - 3.0f*SIG5 + SIG5*SIG5)
#define FB_A2 (SIG5 - SIG5*SIG5)
#define FB_B0 (SIG5S)
#define FB_B1 (SIG5S*(2.0f*SIG5 - 3.0f))
#define FB_B2 (SIG5S*(1.0f - 2.0f*SIG5))

// Accurate prologue helpers.
__device__ __forceinline__ float sigm1(float z) {
    float e = __expf(-z);
    return __fdividef(1.0f, 1.0f + e);
}
__device__ __forceinline__ float tanh_acc(float z) {
    return fmaf(2.0f, sigm1(2.0f * z), -1.0f);
}

// Exact rot63: f in (0,1) -> 2f (f<0.5) or 2f-1 (f>=0.5).
__device__ __forceinline__ float rot63f(float f) {
    float t = f + f;
    float r = t - 1.0f;
    return (t >= 1.0f) ? r : t;
}

// Clamped soft_xor combine from precomputed sigmoids (final-A only).
__device__ __forceinline__ float xorcomb(float xs, float ys) {
    float p = xs * ys;
    float s = xs + ys;
    float u = fmaf(p, -2.0f, s);
    float q = (1.0f + p) - s;
    return __saturatef(fmaf(-p, q, u));
}

#define IVF(x) ((float)(x##ull) * 0x1p-64f)

__global__ void __launch_bounds__(128, 5)
blake2_soft_kernel(const float* __restrict__ msg, float* __restrict__ out, int batch) {
    int i = blockIdx.x * 128 + threadIdx.x;
    if (i >= batch) return;

    const float IVf[8] = {
        IVF(7640891576956012808), IVF(13503953896175478587),
        IVF(4354685564936845355), IVF(11912009170470909681),
        IVF(5840696475078001361), IVF(11170449401992604703),
        IVF(2270897969802886507), IVF(6620516959819538809)
    };

    // ---------------- prologue pass 1: c-channel trajectory per lane q -----
    float A5[4], B5[4], C5[4];           // col-S5 quad coeffs in tx
    float F0[4], F1[4];                  // col-S10 affine in d16c
    float H1v[4], YD0v[4], YS1v[4];      // diag-S9/S10 affine
    float T0cv[4], TS1v[4];              // diag-S5 ty affine
    float BCv[4];                        // base of col-S10 output
#pragma unroll
    for (int q = 0; q < 4; q++) {
        float IVq = IVf[q];
        float sA  = sigm1(10.0f * (IVq - 1.0f));
        float CA1 = IVq - sA;
        float ty5 = tanh_acc(fmaf(CA1, 5.0f, -2.5f));
        float E5  = fmaf(-ty5, ty5, 1.0f) * 0.0625f;
        A5[q] = (0.5f - E5) * 0x1p-24f;
        B5[q] = (-0.5f * ty5) * 0x1p-24f;
        C5[q] = E5 * 0x1p-24f;
        float s9  = sigm1(10.0f * (CA1 - 1.0f));
        float CA2 = CA1 - s9;
        float S2c = fmaf(-10.0f * s9, (1.0f - s9), 1.0f);
        float y0  = sigm1(10.0f * (CA2 - 0.5f));
        float Y1c = 10.0f * y0 * (1.0f - y0) * S2c;
        F0[q] = fmaf(y0, S10B, S10A) + y0 * y0 * S10G;
        F1[q] = fmaf(2.0f * S10G, y0, S10B) * Y1c;
        BCv[q] = rot63f(F0[q]);
        float sb  = sigm1(10.0f * (CA2 - 1.0f));
        float CB1 = CA2 - sb;
        float G1  = fmaf(-10.0f * sb, (1.0f - sb), 1.0f);
        float t0  = tanh_acc(fmaf(CB1, 5.0f, -2.5f));
        T0cv[q] = t0;
        TS1v[q] = 5.0f * fmaf(-t0, t0, 1.0f) * G1 * S2c;
        float sc  = sigm1(10.0f * (CB1 - 1.0f));
        float CB2 = CB1 - sc;
        float G2  = fmaf(-10.0f * sc, (1.0f - sc), 1.0f);
        H1v[q] = G1 * S2c;
        float yd0 = sigm1(10.0f * (CB2 - 0.5f));
        YD0v[q] = yd0;
        YS1v[q] = 10.0f * yd0 * (1.0f - yd0) * G2;
    }

    // ---------------- prologue pass 2: b-channel fold coefficients ---------
    float E0[4], E1[4], E2[4];           // diag-S5: b24d = E0 + E1*b + E2*d16c[qc]
    float P0[4], P1[4], P2[4];           // final-B: xs = P0 + P1*b + P2*b^2
    float Q0[4], Q1[4], Q2[4];           // col-S5 (r>=1): b24 = Q0 + Q1*b + Q2*b^2
    float K0[4];                         // col-S5 (r==0): constant (b = IV)
#pragma unroll
    for (int q = 0; q < 4; q++) {
        int kb = (q + 1) & 3, qc = (q + 2) & 3;
        // diag-S5 fold around (TXd, ty0)
        float TXd = tanh_acc(fmaf(BCv[kb], 5.0f, -2.5f));
        float ty0 = T0cv[qc];
        float omx = fmaf(-TXd, TXd, 1.0f);
        float omy = fmaf(-ty0, ty0, 1.0f);
        float S0  = 0.5f - 0.5f * TXd * ty0 - omx * omy * 0.0625f;
        float dsx = fmaf(TXd, omy * 0.125f, -0.5f * ty0);
        float dsy = fmaf(ty0, omx * 0.125f, -0.5f * TXd);
        E1[q] = 0x1p-24f * dsx * (5.0f * omx);
        E2[q] = 0x1p-24f * dsy * TS1v[qc];
        E0[q] = fmaf(-E1[q], BCv[kb], 0x1p-24f * S0);
        // final-B fold for state word 4+q (ys lane (q+1)&3)
        float ydw = YD0v[(q + 1) & 3];
        float fd0 = fmaf(ydw, S10B, S10A) + ydw * ydw * S10G;
        float BW  = rot63f(fd0);
        float xv  = sigm1(10.0f * (BW - 0.5f));
        float xss = 10.0f * xv * (1.0f - xv);
        float xsc = 50.0f * xv * (1.0f - xv) * (1.0f - 2.0f * xv);
        P2[q] = xsc;
        P1[q] = fmaf(-2.0f * xsc, BW, xss);
        P0[q] = fmaf(fmaf(xsc, BW, -xss), BW, xv);
        // base of state word 4+q (final-B output at b=BW, d16d~0)
        float Bst = fmaf(xv, fmaf(xv, FB_A2, FB_A1), SIG5);
        // col-S5 quadratic in b around Bst (this lane's own b = word 4+q)
        float tx0 = tanh_acc(fmaf(Bst, 5.0f, -2.5f));
        float tx1 = 5.0f * fmaf(-tx0, tx0, 1.0f);
        float u0  = fmaf(-tx1, Bst, tx0);
        Q0[q] = fmaf(u0, fmaf(u0, C5[q], B5[q]), A5[q]);
        Q1[q] = tx1 * fmaf(2.0f * u0, C5[q], B5[q]);
        Q2[q] = C5[q] * tx1 * tx1;
        // r=0 constant: b = IV[4+q] exactly
        float txI = tanh_acc(fmaf(IVf[4 + q], 5.0f, -2.5f));
        K0[q] = fmaf(txI, fmaf(txI, C5[q], B5[q]), A5[q]);
    }

    // -------- load message --------
    float m[16];
    {
        const float4* mp = reinterpret_cast<const float4*>(msg) + (size_t)i * 4;
        float4 q0 = mp[0], q1 = mp[1], q2 = mp[2], q3 = mp[3];
        m[0] = q0.x;  m[1] = q0.y;  m[2] = q0.z;  m[3] = q0.w;
        m[4] = q1.x;  m[5] = q1.y;  m[6] = q1.z;  m[7] = q1.w;
        m[8] = q2.x;  m[9] = q2.y;  m[10] = q2.z; m[11] = q2.w;
        m[12] = q3.x; m[13] = q3.y; m[14] = q3.z; m[15] = q3.w;
    }

    // Live state: a-words v[0..3], b-words v[4..7].
    float v[8];
#pragma unroll
    for (int j = 0; j < 8; j++) v[j] = IVf[j];

// soft_add batch over the 4 a-words; epilogue fused into FFMA.
#define SA4(ADDEND)                                                           \
    {                                                                         \
        float s_[4], w_[4];                                                   \
        _Pragma("unroll") for (int q = 0; q < 4; q++) s_[q] = v[q] + (ADDEND); \
        _Pragma("unroll") for (int q = 0; q < 4; q++) w_[q] = fmaf(s_[q], -K10, K10); \
        float d0 = 1.0f + ex2a(w_[0]);                                        \
        float d1 = 1.0f + ex2a(w_[1]);                                        \
        float d2 = 1.0f + ex2a(w_[2]);                                        \
        float d3 = 1.0f + ex2a(w_[3]);                                        \
        float p01 = d0 * d1, p23 = d2 * d3;                                   \
        float R   = rcpa(p01 * p23);                                          \
        float R01 = R * p23, R23 = R * p01;                                   \
        v[0] = fmaf(-R01, d1, s_[0]);                                         \
        v[1] = fmaf(-R01, d0, s_[1]);                                         \
        v[2] = fmaf(-R23, d3, s_[2]);                                         \
        v[3] = fmaf(-R23, d2, s_[3]);                                         \
    }

#pragma unroll 1
    for (int r = 0; r < 10; r++) {
        float d16c[4], d16d[4], ysd[4];

        // ================= column step =====================================
        SA4(v[4 + q]);          // S1
        SA4(m[2 * q]);          // S2
        // S5: b24 quadratic in b (b = state word, near Bst); r=0: constant
        float b24[4];
#pragma unroll
        for (int q = 0; q < 4; q++) {
            float b = v[4 + q];
            b24[q] = fmaf(b, fmaf(b, Q2[q], Q1[q]), Q0[q]);
        }
        if (r == 0) {
#pragma unroll
            for (int q = 0; q < 4; q++) b24[q] = K0[q];
        }
        SA4(b24[q]);            // S6
        SA4(m[2 * q + 1]);      // S7
        // S8: d16c = quad(tanh(5a-2.5))
#pragma unroll
        for (int q = 0; q < 4; q++) {
            float ty = tanha(fmaf(v[q], 5.0f, -2.5f));
            d16c[q] = fmaf(ty, fmaf(ty, C16, B16), A16);
        }
        // S10: b = rot63f(F0 + F1*d16c)
#pragma unroll
        for (int q = 0; q < 4; q++)
            v[4 + q] = rot63f(fmaf(d16c[q], F1[q], F0[q]));

        // ================= diagonal step ===================================
        SA4(v[4 + ((q + 1) & 3)]);   // S1
        SA4(m[8 + 2 * q]);           // S2
        // S5: b24d affine in (b, d16c[qc])
        float b24d[4];
#pragma unroll
        for (int q = 0; q < 4; q++) {
            float b = v[4 + ((q + 1) & 3)];
            b24d[q] = fmaf(d16c[(q + 2) & 3], E2[q], fmaf(b, E1[q], E0[q]));
        }
        SA4(b24d[q]);                // S6
        SA4(m[9 + 2 * q]);           // S7

        // final-A xs batch FIRST (accurate sigmoids of the final a-words);
        // diag-S8 ty comes free: ty = 2*xs - 1.
        float xs[4];
        {
            float wx[4];
#pragma unroll
            for (int j = 0; j < 4; j++) wx[j] = fmaf(v[j], -K10, KH);
            float d0 = 1.0f + ex2a(wx[0]);
            float d1 = 1.0f + ex2a(wx[1]);
            float d2 = 1.0f + ex2a(wx[2]);
            float d3 = 1.0f + ex2a(wx[3]);
            float p01 = d0 * d1, p23 = d2 * d3;
            float R   = rcpa(p01 * p23);
            float R01 = R * p23, R23 = R * p01;
            xs[0] = R01 * d1; xs[1] = R01 * d0;
            xs[2] = R23 * d3; xs[3] = R23 * d2;
        }
        // S8: d16d from ty = 2*xs-1
#pragma unroll
        for (int q = 0; q < 4; q++) {
            float ty = fmaf(2.0f, xs[q], -1.0f);
            d16d[q] = fmaf(ty, fmaf(ty, C16, B16), A16);
        }
        // S10: w = H1*d16c + d16d ; ys = YD0 + YS1*w ; f quad; b = rot63f(f)
#pragma unroll
        for (int q = 0; q < 4; q++) {
            int qc = (q + 2) & 3;
            float w  = fmaf(H1v[qc], d16c[qc], d16d[q]);
            float ys = fmaf(YS1v[qc], w, YD0v[qc]);
            ysd[q]   = ys;
            float f  = fmaf(ys, fmaf(ys, S10G, S10B), S10A);
            v[4 + ((q + 1) & 3)] = rot63f(f);
        }

        // final-A: state_j = soft_xor(xs_j, ysd[(j+2)&3])
#pragma unroll
        for (int j = 0; j < 4; j++) v[j] = xorcomb(xs[j], ysd[(j + 2) & 3]);

        // final-B: xs quadratic in b; xor with ysl expansion
#pragma unroll
        for (int k = 0; k < 4; k++) {
            float b  = v[4 + k];
            float x2 = fmaf(b, fmaf(b, P2[k], P1[k]), P0[k]);
            float f0 = fmaf(x2, fmaf(x2, FB_A2, FB_A1), SIG5);
            float g  = fmaf(x2, fmaf(x2, FB_B2, FB_B1), FB_B0);
            v[4 + k] = fmaf(d16d[(k + 1) & 3], g, f0);
        }
    }

    float4* op = reinterpret_cast<float4*>(out) + (size_t)i * 2;
    op[0] = make_float4(v[0], v[1], v[2], v[3]);
    op[1] = make_float4(v[4], v[5], v[6], v[7]);
}

extern "C" void kernel_launch(void* const* d_in, const int* in_sizes, int n_in,
                              void* d_out, int out_size) {
    const float* msg = (const float*)d_in[0];
    float* out = (float*)d_out;
    int batch = in_sizes[0] / 16;
    int blocks = (batch + 127) / 128;
    blake2_soft_kernel<<<blocks, 128>>>(msg, out, batch);
}

// round 17
// speedup vs baseline: 2.1932x; 1.1220x over previous
#include <cuda_runtime.h>
#include <cstdint>

// ---------------------------------------------------------------------------
// Blake2Cipher soft-hash, fp32 — R13c: compile-time fold constants, baked as
// immediates. (R16 fix: constexpr helpers marked __host__ __device__, CC made
// a function-local constexpr so device code sees compile-time literals.)
// ---------------------------------------------------------------------------

// ---- constexpr double math (compile-time only) ----------------------------
__host__ __device__ constexpr double cexp_(double x) {
    double ax = x < 0 ? -x : x;
    int k = (int)(ax / 0.6931471805599453 + 0.5);
    if (x < 0) k = -k;
    double r = x - (double)k * 0.6931471805599453;
    double s = 1.0, t = 1.0;
    for (int i = 1; i < 26; i++) { t *= r / (double)i; s += t; }
    double p = 1.0;
    int kk = k < 0 ? -k : k;
    for (int i = 0; i < kk; i++) p *= 2.0;
    return k >= 0 ? s * p : s / p;
}
__host__ __device__ constexpr double csig_(double z) { return 1.0 / (1.0 + cexp_(-z)); }
__host__ __device__ constexpr double ctanh_(double z) { return 2.0 * csig_(2.0 * z) - 1.0; }

struct CCt {
    float Q0[4] = {}, Q1[4] = {}, Q2[4] = {}, K0[4] = {};     // col-S5 quad / r0
    float CF0[4] = {}, CF1[4] = {}, F0r[4] = {}, F1r[4] = {}; // col-S10
    bool  colSafe[4] = {};
    float E0[4] = {}, E1[4] = {}, E2[4] = {};                 // diag-S5 affine
    float H1[4] = {}, YD0[4] = {}, YS1[4] = {}, D0[4] = {};   // diag-S9/S10
    bool  dSafe[4] = {};
    float P0[4] = {}, P1[4] = {}, P2[4] = {};                 // final-B xs quad
    float A16 = 0, B16 = 0, C16 = 0;                          // d16 quad coeffs
    float DSB = 0, DSG = 0;                                   // diag-S10 fused
    float S10Af = 0, S10Bf = 0, S10Gf = 0;                    // fallback quad
    float FBA1 = 0, FBA2 = 0, FBB0 = 0, FBB1 = 0, FBB2 = 0, SIG5f = 0;
};

__host__ __device__ constexpr CCt make_cc() {
    CCt c{};
    constexpr double W = 18446744073709551616.0;
    const double IV[8] = {
        (double)(float)7640891576956012808ull / W,
        (double)(float)13503953896175478587ull / W,
        (double)(float)4354685564936845355ull / W,
        (double)(float)11912009170470909681ull / W,
        (double)(float)5840696475078001361ull / W,
        (double)(float)11170449401992604703ull / W,
        (double)(float)2270897969802886507ull / W,
        (double)(float)6620516959819538809ull / W
    };
    const double p24 = 1.0 / 16777216.0, p16 = 1.0 / 65536.0;

    // global folds
    const double th25 = ctanh_(2.5);
    const double dq16 = (1.0 - th25 * th25) / 16.0;
    c.A16 = (float)((0.5 - dq16) * p16);
    c.B16 = (float)((0.5 * th25) * p16);
    c.C16 = (float)(dq16 * p16);
    const double sg5  = csig_(-5.0);
    const double s10a = sg5;
    const double s10b = (1.0 - 2.0 * sg5) - sg5 * (1.0 - sg5);
    const double s10g = sg5 * (1.0 - sg5);
    c.DSB = (float)(2.0 * s10b);
    c.DSG = (float)(2.0 * s10g);
    c.S10Af = (float)s10a; c.S10Bf = (float)s10b; c.S10Gf = (float)s10g;
    const double sig5s = 10.0 * sg5 * (1.0 - sg5);
    c.FBA1 = (float)(1.0 - 3.0 * sg5 + sg5 * sg5);
    c.FBA2 = (float)(sg5 - sg5 * sg5);
    c.FBB0 = (float)sig5s;
    c.FBB1 = (float)(sig5s * (2.0 * sg5 - 3.0));
    c.FBB2 = (float)(sig5s * (1.0 - 2.0 * sg5));
    c.SIG5f = (float)sg5;

    const double dmax = (0.5 * (1.0 + th25)) * p16 * 1.05;  // d16 upper bound

    double A5[4] = {}, B5[4] = {}, C5[4] = {};
    double t0a[4] = {}, TS1a[4] = {}, yd0a[4] = {}, BCa[4] = {};

    // pass 1: c-channel trajectory per lane q
    for (int q = 0; q < 4; q++) {
        double IVq = IV[q];
        double sA  = csig_(10.0 * (IVq - 1.0));
        double CA1 = IVq - sA;
        double ty5 = ctanh_(5.0 * CA1 - 2.5);
        double E5  = (1.0 - ty5 * ty5) / 16.0;
        A5[q] = (0.5 - E5) * p24;
        B5[q] = (-0.5 * ty5) * p24;
        C5[q] = E5 * p24;
        double s9  = csig_(10.0 * (CA1 - 1.0));
        double CA2 = CA1 - s9;
        double S2c = 1.0 - 10.0 * s9 * (1.0 - s9);
        double y0  = csig_(10.0 * (CA2 - 0.5));
        double Y1c = 10.0 * y0 * (1.0 - y0) * S2c;
        double F0  = s10a + s10b * y0 + s10g * y0 * y0;
        double F1  = (s10b + 2.0 * s10g * y0) * Y1c;
        double lo  = F0, hi = F0 + F1 * dmax;
        bool bhi   = (F0 >= 0.5);
        c.colSafe[q] = ((lo - 0.5) * (hi - 0.5)) > 1e-12;
        c.CF1[q] = (float)(2.0 * F1);
        c.CF0[q] = (float)(bhi ? 2.0 * F0 - 1.0 : 2.0 * F0);
        c.F0r[q] = (float)F0; c.F1r[q] = (float)F1;
        BCa[q] = bhi ? 2.0 * F0 - 1.0 : 2.0 * F0;
        double sb  = csig_(10.0 * (CA2 - 1.0));
        double CB1 = CA2 - sb;
        double G1  = 1.0 - 10.0 * sb * (1.0 - sb);
        t0a[q] = ctanh_(5.0 * CB1 - 2.5);
        TS1a[q] = 5.0 * (1.0 - t0a[q] * t0a[q]) * G1 * S2c;
        double sc  = csig_(10.0 * (CB1 - 1.0));
        double CB2 = CB1 - sc;
        double G2  = 1.0 - 10.0 * sc * (1.0 - sc);
        c.H1[q] = (float)(G1 * S2c);
        double yd0 = csig_(10.0 * (CB2 - 0.5));
        yd0a[q] = yd0;
        double YS1 = 10.0 * yd0 * (1.0 - yd0) * G2;
        c.YD0[q] = (float)yd0; c.YS1[q] = (float)YS1;
        double f0d = s10a + s10b * yd0 + s10g * yd0 * yd0;
        double wmax = (G1 * S2c + 1.0) * dmax;
        double df  = (s10b + 2.0 * s10g) * (YS1 < 0 ? -YS1 : YS1) * wmax;
        bool dhi = (f0d >= 0.5);
        c.dSafe[q] = ((f0d - 0.5 - df) * (f0d - 0.5 + df)) > 1e-12;
        c.D0[q] = (float)(2.0 * s10a - (dhi ? 1.0 : 0.0));
    }

    // pass 2: b-channel fold coefficients per lane q
    for (int q = 0; q < 4; q++) {
        int kb = (q + 1) & 3, qc = (q + 2) & 3;
        double TXd = ctanh_(5.0 * BCa[kb] - 2.5);
        double omx = 1.0 - TXd * TXd;
        double omy = 1.0 - t0a[qc] * t0a[qc];
        double S0  = 0.5 - 0.5 * TXd * t0a[qc] - omx * omy / 16.0;
        double dsx = 0.125 * TXd * omy - 0.5 * t0a[qc];
        double dsy = 0.125 * t0a[qc] * omx - 0.5 * TXd;
        double E1  = p24 * dsx * 5.0 * omx;
        double E2  = p24 * dsy * TS1a[qc];
        c.E1[q] = (float)E1;
        c.E2[q] = (float)E2;
        c.E0[q] = (float)(-E1 * BCa[kb] + p24 * S0);
        double ydw = yd0a[(q + 1) & 3];
        double fd0 = s10a + s10b * ydw + s10g * ydw * ydw;
        double BW  = (fd0 >= 0.5) ? 2.0 * fd0 - 1.0 : 2.0 * fd0;
        double xv  = csig_(10.0 * (BW - 0.5));
        double xss = 10.0 * xv * (1.0 - xv);
        double xsc = 50.0 * xv * (1.0 - xv) * (1.0 - 2.0 * xv);
        c.P2[q] = (float)xsc;
        c.P1[q] = (float)(xss - 2.0 * xsc * BW);
        c.P0[q] = (float)(xv - xss * BW + xsc * BW * BW);
        double Bst = sg5 + (1.0 - 3.0 * sg5 + sg5 * sg5) * xv
                   + (sg5 - sg5 * sg5) * xv * xv;
        double tx0 = ctanh_(5.0 * Bst - 2.5);
        double tx1 = 5.0 * (1.0 - tx0 * tx0);
        double u0  = tx0 - tx1 * Bst;
        c.Q0[q] = (float)(A5[q] + B5[q] * u0 + C5[q] * u0 * u0);
        c.Q1[q] = (float)(tx1 * (B5[q] + 2.0 * C5[q] * u0));
        c.Q2[q] = (float)(C5[q] * tx1 * tx1);
        double txI = ctanh_(5.0 * IV[4 + q] - 2.5);
        c.K0[q] = (float)(A5[q] + B5[q] * txI + C5[q] * txI * txI);
    }
    return c;
}

// ---- device helpers -------------------------------------------------------
__device__ __forceinline__ float ex2a(float x){ float r; asm("ex2.approx.f32 %0, %1;" : "=f"(r) : "f"(x)); return r; }
__device__ __forceinline__ float rcpa(float x){ float r; asm("rcp.approx.f32 %0, %1;" : "=f"(r) : "f"(x)); return r; }
__device__ __forceinline__ float tanha(float x){ float r; asm("tanh.approx.f32 %0, %1;" : "=f"(r) : "f"(x)); return r; }

#define K10   14.42695041f    // 10*log2(e)
#define KH     7.213475205f   // 5*log2(e)

// Exact rot63 (fallback when branch not statically safe).
__device__ __forceinline__ float rot63f(float f) {
    float t = f + f;
    float r = t - 1.0f;
    return (t >= 1.0f) ? r : t;
}

// Clamped soft_xor combine from precomputed sigmoids (final-A).
__device__ __forceinline__ float xorcomb(float xs, float ys) {
    float p = xs * ys;
    float s = xs + ys;
    float u = fmaf(p, -2.0f, s);
    float q = (1.0f + p) - s;
    return __saturatef(fmaf(-p, q, u));
}

// soft_add batch over the 4 a-words; epilogue fused into FFMA.
__device__ __forceinline__ void sa4(float v[8], float a0, float a1, float a2, float a3) {
    float s0 = v[0] + a0, s1 = v[1] + a1, s2 = v[2] + a2, s3 = v[3] + a3;
    float d0 = 1.0f + ex2a(fmaf(s0, -K10, K10));
    float d1 = 1.0f + ex2a(fmaf(s1, -K10, K10));
    float d2 = 1.0f + ex2a(fmaf(s2, -K10, K10));
    float d3 = 1.0f + ex2a(fmaf(s3, -K10, K10));
    float p01 = d0 * d1, p23 = d2 * d3;
    float R   = rcpa(p01 * p23);
    float R01 = R * p23, R23 = R * p01;
    v[0] = fmaf(-R01, d1, s0);
    v[1] = fmaf(-R01, d0, s1);
    v[2] = fmaf(-R23, d3, s2);
    v[3] = fmaf(-R23, d2, s3);
}

template <bool R0>
__device__ __forceinline__ void round_fn(float v[8], const float m[16]) {
    constexpr CCt CC = make_cc();   // compile-time; values become immediates
    float d16c[4], d16d[4], ysd[4];

    // ================= column step ========================================
    sa4(v, v[4], v[5], v[6], v[7]);                 // S1
    sa4(v, m[0], m[2], m[4], m[6]);                 // S2
    // S5: b24 quadratic in b (r0: exact IV constant)
    float b24[4];
#pragma unroll
    for (int q = 0; q < 4; q++) {
        if (R0) {
            b24[q] = CC.K0[q];
        } else {
            float b = v[4 + q];
            b24[q] = fmaf(b, fmaf(b, CC.Q2[q], CC.Q1[q]), CC.Q0[q]);
        }
    }
    sa4(v, b24[0], b24[1], b24[2], b24[3]);         // S6
    sa4(v, m[1], m[3], m[5], m[7]);                 // S7
    // S8: d16c = quad(tanh(5a-2.5))
#pragma unroll
    for (int q = 0; q < 4; q++) {
        float ty = tanha(fmaf(v[q], 5.0f, -2.5f));
        d16c[q] = fmaf(ty, fmaf(ty, CC.C16, CC.B16), CC.A16);
    }
    // S10: b = CF0 + CF1*d16c  (branch static) or fallback
#pragma unroll
    for (int q = 0; q < 4; q++) {
        if (CC.colSafe[q]) {
            v[4 + q] = fmaf(d16c[q], CC.CF1[q], CC.CF0[q]);
        } else {
            v[4 + q] = rot63f(fmaf(d16c[q], CC.F1r[q], CC.F0r[q]));
        }
    }

    // ================= diagonal step ======================================
    sa4(v, v[5], v[6], v[7], v[4]);                 // S1 (b lanes rotated +1)
    sa4(v, m[8], m[10], m[12], m[14]);              // S2
    // S5: b24d affine in (b, d16c[qc])
    float b24d[4];
#pragma unroll
    for (int q = 0; q < 4; q++) {
        float b = v[4 + ((q + 1) & 3)];
        b24d[q] = fmaf(d16c[(q + 2) & 3], CC.E2[q], fmaf(b, CC.E1[q], CC.E0[q]));
    }
    sa4(v, b24d[0], b24d[1], b24d[2], b24d[3]);     // S6
    sa4(v, m[9], m[11], m[13], m[15]);              // S7

    // final-A xs batch (accurate sigmoids of final a-words); diag-S8 ty = 2xs-1
    float xs[4];
    {
        float d0 = 1.0f + ex2a(fmaf(v[0], -K10, KH));
        float d1 = 1.0f + ex2a(fmaf(v[1], -K10, KH));
        float d2 = 1.0f + ex2a(fmaf(v[2], -K10, KH));
        float d3 = 1.0f + ex2a(fmaf(v[3], -K10, KH));
        float p01 = d0 * d1, p23 = d2 * d3;
        float R   = rcpa(p01 * p23);
        float R01 = R * p23, R23 = R * p01;
        xs[0] = R01 * d1; xs[1] = R01 * d0;
        xs[2] = R23 * d3; xs[3] = R23 * d2;
    }
#pragma unroll
    for (int q = 0; q < 4; q++) {
        float ty = fmaf(2.0f, xs[q], -1.0f);
        d16d[q] = fmaf(ty, fmaf(ty, CC.C16, CC.B16), CC.A16);
    }
    // S10: w -> ys -> b (fused quad, branch static) per lane
#pragma unroll
    for (int q = 0; q < 4; q++) {
        int qc = (q + 2) & 3;
        float w  = fmaf(CC.H1[qc], d16c[qc], d16d[q]);
        float ys = fmaf(CC.YS1[qc], w, CC.YD0[qc]);
        ysd[q]   = ys;
        if (CC.dSafe[qc]) {
            v[4 + ((q + 1) & 3)] = fmaf(ys, fmaf(ys, CC.DSG, CC.DSB), CC.D0[qc]);
        } else {
            float f = fmaf(ys, fmaf(ys, CC.S10Gf, CC.S10Bf), CC.S10Af);
            v[4 + ((q + 1) & 3)] = rot63f(f);
        }
    }

    // final-A: state_j = soft_xor(xs_j, ysd[(j+2)&3])
#pragma unroll
    for (int j = 0; j < 4; j++) v[j] = xorcomb(xs[j], ysd[(j + 2) & 3]);

    // final-B: xs quadratic in b; xor with ysl expansion
#pragma unroll
    for (int k = 0; k < 4; k++) {
        float b  = v[4 + k];
        float x2 = fmaf(b, fmaf(b, CC.P2[k], CC.P1[k]), CC.P0[k]);
        float f0 = fmaf(x2, fmaf(x2, CC.FBA2, CC.FBA1), CC.SIG5f);
        float g  = fmaf(x2, fmaf(x2, CC.FBB2, CC.FBB1), CC.FBB0);
        v[4 + k] = fmaf(d16d[(k + 1) & 3], g, f0);
    }
}

#define IVF(x) ((float)(x##ull) * 0x1p-64f)

__global__ void __launch_bounds__(128, 5)
blake2_soft_kernel(const float* __restrict__ msg, float* __restrict__ out, int batch) {
    int i = blockIdx.x * 128 + threadIdx.x;
    if (i >= batch) return;

    float m[16];
    {
        const float4* mp = reinterpret_cast<const float4*>(msg) + (size_t)i * 4;
        float4 q0 = mp[0], q1 = mp[1], q2 = mp[2], q3 = mp[3];
        m[0] = q0.x;  m[1] = q0.y;  m[2] = q0.z;  m[3] = q0.w;
        m[4] = q1.x;  m[5] = q1.y;  m[6] = q1.z;  m[7] = q1.w;
        m[8] = q2.x;  m[9] = q2.y;  m[10] = q2.z; m[11] = q2.w;
        m[12] = q3.x; m[13] = q3.y; m[14] = q3.z; m[15] = q3.w;
    }

    float v[8] = {
        IVF(7640891576956012808), IVF(13503953896175478587),
        IVF(4354685564936845355), IVF(11912009170470909681),
        IVF(5840696475078001361), IVF(11170449401992604703),
        IVF(2270897969802886507), IVF(6620516959819538809)
    };

    round_fn<true>(v, m);          // round 0 (b = IV exactly at col-S5)
#pragma unroll 1
    for (int r = 1; r < 10; r++)
        round_fn<false>(v, m);

    float4* op = reinterpret_cast<float4*>(out) + (size_t)i * 2;
    op[0] = make_float4(v[0], v[1], v[2], v[3]);
    op[1] = make_float4(v[4], v[5], v[6], v[7]);
}

extern "C" void kernel_launch(void* const* d_in, const int* in_sizes, int n_in,
                              void* d_out, int out_size) {
    const float* msg = (const float*)d_in[0];
    float* out = (float*)d_out;
    int batch = in_sizes[0] / 16;
    int blocks = (batch + 127) / 128;
    blake2_soft_kernel<<<blocks, 128>>>(msg, out, batch);
}